// round 13
// baseline (speedup 1.0000x reference)
#include <cuda_runtime.h>
#include <cuda_fp16.h>
#include <cstdint>
#include <math.h>

// ===================== problem constants =====================
#define D 128
#define NROWS (64 * 4096)          // B*T = 262144
#define NTILES (NROWS / 128)       // 2048
#define GRID_MAIN 148
#define NTHREADS 512               // warps 0-7: GEMM1 producers, 8-15: GEMM2 consumers

// ===================== helpers =====================
__device__ __forceinline__ uint32_t smem_u32(const void* p) {
    uint32_t a;
    asm("{ .reg .u64 t; cvta.to.shared.u64 t, %1; cvt.u32.u64 %0, t; }" : "=r"(a) : "l"(p));
    return a;
}
__device__ __forceinline__ uint32_t pack2h(__half a, __half b) {
    return (uint32_t)__half_as_ushort(a) | ((uint32_t)__half_as_ushort(b) << 16);
}
__device__ __forceinline__ void split2h(float x0, float x1, uint32_t& hi, uint32_t& lo) {
    __half h0 = __float2half_rn(x0), h1 = __float2half_rn(x1);
    hi = pack2h(h0, h1);
    lo = pack2h(__float2half_rn(x0 - __half2float(h0)),
                __float2half_rn(x1 - __half2float(h1)));
}
__device__ __forceinline__ float gelu_exact(float v) {
    return 0.5f * v * (1.0f + erff(v * 0.70710678118654752f));
}

#define MMA(c0, c1, c2, c3, a0, a1, a2, a3, b0, b1)                                   \
    asm volatile("mma.sync.aligned.m16n8k16.row.col.f32.f16.f16.f32 "                 \
                 "{%0,%1,%2,%3}, {%4,%5,%6,%7}, {%8,%9}, {%0,%1,%2,%3};"              \
                 : "+f"(c0), "+f"(c1), "+f"(c2), "+f"(c3)                             \
                 : "r"(a0), "r"(a1), "r"(a2), "r"(a3), "r"(b0), "r"(b1))

#define LDSM4(r0, r1, r2, r3, addr)                                                    \
    asm volatile("ldmatrix.sync.aligned.m8n8.x4.shared.b16 {%0,%1,%2,%3}, [%4];"       \
                 : "=r"(r0), "=r"(r1), "=r"(r2), "=r"(r3) : "r"(addr))

#define BARN(id, cnt) asm volatile("bar.sync %0, %1;" :: "r"(id), "r"(cnt) : "memory")

// ===================== SMEM map =====================
// x image: 128 rows x 256B (fp16), XOR-16B swizzle per row. h ping-pong same layout.
#define SXH  0          // 32 KB
#define SXL  32768      // 32 KB
#define SH0H 65536      // h buffer 0 hi (also W1 B-image during precompute)
#define SH0L 98304      // h buffer 0 lo (also T1 B-image during precompute)
#define SH1H 131072     // h buffer 1 hi (also Wout B-image during precompute)
#define SH1L 163840     // h buffer 1 lo
#define SB1  196608
#define SB2  197120
#define SGAM 197632     // gamma (bg during precompute)
#define SBET 198144
#define SRED 198656     // 4 KB: LN partials / bg scratch
#define SMEM_BYTES 202752

#define SWIMG1 SH0H     // W1 image
#define SWIMG2 SH0L     // T1 image
#define SWIMG3 SH1H     // Wout image

// Precompute k-step: 16 rows x 64 cols, 2-term A, single-fp16 B image. c[8][4].
__device__ __forceinline__ void pre_kstep(float (&c)[8][4],
                                          const uint32_t* aH, const uint32_t* aL,
                                          uint32_t base, uint32_t sAdd) {
#pragma unroll
    for (int j = 0; j < 4; j++) {
        uint32_t b0, b1, b2, b3;
        LDSM4(b0, b1, b2, b3, base + j * 4096 + sAdd);
        MMA(c[2 * j][0], c[2 * j][1], c[2 * j][2], c[2 * j][3],
            aH[0], aH[1], aH[2], aH[3], b0, b1);
        MMA(c[2 * j + 1][0], c[2 * j + 1][1], c[2 * j + 1][2], c[2 * j + 1][3],
            aH[0], aH[1], aH[2], aH[3], b2, b3);
        MMA(c[2 * j][0], c[2 * j][1], c[2 * j][2], c[2 * j][3],
            aL[0], aL[1], aL[2], aL[3], b0, b1);
        MMA(c[2 * j + 1][0], c[2 * j + 1][1], c[2 * j + 1][2], c[2 * j + 1][3],
            aL[0], aL[1], aL[2], aL[3], b2, b3);
    }
}

// A fragments (16 rows x k16) from a global fp32 row pointer (precompute only)
__device__ __forceinline__ void load_a_frags(const float* arow, int s,
                                             uint32_t (&aH)[4], uint32_t (&aL)[4]) {
    float2 v00 = *(const float2*)(arow + 16 * s);
    float2 v10 = *(const float2*)(arow + 16 * s + 8 * D);
    float2 v01 = *(const float2*)(arow + 16 * s + 8);
    float2 v11 = *(const float2*)(arow + 16 * s + 8 * D + 8);
    split2h(v00.x, v00.y, aH[0], aL[0]);
    split2h(v10.x, v10.y, aH[1], aL[1]);
    split2h(v01.x, v01.y, aH[2], aL[2]);
    split2h(v11.x, v11.y, aH[3], aL[3]);
}

// Store one fp32 into a single-fp16 B-image ([n][k], XOR swizzle) at (k=m, n).
__device__ __forceinline__ void store_bimg(char* smem, uint32_t dst, int m, int n, float v) {
    uint32_t off = ((uint32_t)(n * 256 + m * 2)) ^ (((uint32_t)n & 7u) << 4);
    *(__half*)(smem + dst + off) = __float2half_rn(v);
}

// ===================== single fused kernel =====================
__global__ void __launch_bounds__(NTHREADS, 1)
lgn_main(const float* __restrict__ x, const float* __restrict__ graph,
         const float* __restrict__ W_msg, const float* __restrict__ b_msg,
         const float* __restrict__ W_upd, const float* __restrict__ b_upd,
         const float* __restrict__ Wout, const float* __restrict__ bout,
         const float* __restrict__ gamma, const float* __restrict__ beta,
         float* __restrict__ out) {
    extern __shared__ char smem[];
    const uint32_t sb = smem_u32(smem);
    const int tid = threadIdx.x;
    const int wid = tid >> 5;
    const int l = tid & 31;
    const int quad = l >> 2;
    const int qid = l & 3;

    // B-image ldmatrix lane constants
    const uint32_t nlane = ((l >> 4) & 1) * 8 + (l & 7);
    const uint32_t laneN = nlane * 256;
    const uint32_t xorv  = (nlane & 7) << 4;
    const uint32_t kl2   = ((l >> 3) & 1) * 16;

    // A-image ldmatrix lane constants
    const uint32_t arow  = (l & 7) + ((l >> 3) & 1) * 8;
    const uint32_t akadd = ((l >> 4) & 1) * 16;
    const uint32_t axor  = (l & 7) << 4;
    const uint32_t aoff  = arow * 256;

    const int bx = blockIdx.x;
    const int n = (NTILES - bx + GRID_MAIN - 1) / GRID_MAIN;

    // ================= precompute (all 16 warps) =================
    // warp geometry: rows 16*(wid&7), cols 64*(wid>>3)
    const int prow = wid & 7;
    const int phalf = wid >> 3;
    const uint32_t pbase = (uint32_t)phalf * 16384 + laneN;
    const int pmA = prow * 16 + quad;
    const int pmB = pmA + 8;

    // P0: stage Wb = W_upd[128:] -> SWIMG1; bg partials
    for (int idx = tid; idx < D * D; idx += NTHREADS) {
        int k = idx >> 7, nn = idx & 127;
        store_bimg(smem, SWIMG1, k, nn, W_upd[(D + k) * D + nn]);
    }
    {
        int j = tid & 127, hh = tid >> 7;   // hh 0..3
        float p = 0.f;
#pragma unroll 8
        for (int gg = hh * 32; gg < hh * 32 + 32; gg++)
            p += b_msg[gg] * graph[gg * D + j];
        ((float*)(smem + SRED))[tid] = p;
    }
    __syncthreads();
    if (tid < D) {
        const float* sr = (const float*)(smem + SRED);
        ((float*)(smem + SGAM))[tid] = sr[tid] + sr[tid + 128] + sr[tid + 256] + sr[tid + 384];
    }

    // P1: T1 = graph @ Wb -> SWIMG2 (T1^T B-image)
    {
        float c[8][4];
#pragma unroll
        for (int j = 0; j < 8; j++) { c[j][0] = c[j][1] = c[j][2] = c[j][3] = 0.f; }
        const float* ar = graph + (size_t)pmA * D + qid * 2;
#pragma unroll
        for (int s = 0; s < 8; s++) {
            uint32_t aH[4], aL[4];
            load_a_frags(ar, s, aH, aL);
            pre_kstep(c, aH, aL, sb + SWIMG1, pbase + (((uint32_t)(32 * s) + kl2) ^ xorv));
        }
#pragma unroll
        for (int j = 0; j < 8; j++) {
            int n0 = phalf * 64 + 8 * j + qid * 2;
            store_bimg(smem, SWIMG2, pmA, n0,     c[j][0]);
            store_bimg(smem, SWIMG2, pmA, n0 + 1, c[j][1]);
            store_bimg(smem, SWIMG2, pmB, n0,     c[j][2]);
            store_bimg(smem, SWIMG2, pmB, n0 + 1, c[j][3]);
        }
    }
    __syncthreads();

    // P2: W1 = W_upd[:128] + W_msg @ T1 -> SWIMG1
    {
        float c[8][4];
#pragma unroll
        for (int j = 0; j < 8; j++) { c[j][0] = c[j][1] = c[j][2] = c[j][3] = 0.f; }
        const float* ar = W_msg + (size_t)pmA * D + qid * 2;
#pragma unroll
        for (int s = 0; s < 8; s++) {
            uint32_t aH[4], aL[4];
            load_a_frags(ar, s, aH, aL);
            pre_kstep(c, aH, aL, sb + SWIMG2, pbase + (((uint32_t)(32 * s) + kl2) ^ xorv));
        }
#pragma unroll
        for (int j = 0; j < 8; j++) {
            int n0 = phalf * 64 + 8 * j + qid * 2;
            float2 tA = *(const float2*)(W_upd + (size_t)pmA * D + n0);
            float2 tB = *(const float2*)(W_upd + (size_t)pmB * D + n0);
            store_bimg(smem, SWIMG1, pmA, n0,     c[j][0] + tA.x);
            store_bimg(smem, SWIMG1, pmA, n0 + 1, c[j][1] + tA.y);
            store_bimg(smem, SWIMG1, pmB, n0,     c[j][2] + tB.x);
            store_bimg(smem, SWIMG1, pmB, n0 + 1, c[j][3] + tB.y);
        }
    }
    __syncthreads();

    // P3: stage Wout -> SWIMG3; b1 = b_upd + bg @ W_upd[128:]
    for (int idx = tid; idx < D * D; idx += NTHREADS) {
        int k = idx >> 7, nn = idx & 127;
        store_bimg(smem, SWIMG3, k, nn, Wout[k * D + nn]);
    }
    if (tid < D) {
        const float* bgv = (const float*)(smem + SGAM);
        float acc = b_upd[tid];
#pragma unroll 8
        for (int h = 0; h < D; h++)
            acc += bgv[h] * W_upd[(D + h) * D + tid];
        ((float*)(smem + SB1))[tid] = acc;
    }
    __syncthreads();
    if (tid < D) {
        ((float*)(smem + SB2))[tid]  = bout[tid];
        ((float*)(smem + SGAM))[tid] = gamma[tid];
        ((float*)(smem + SBET))[tid] = beta[tid];
    }
    __syncthreads();

    // P4: preload this warp's 32-col weight quarter into registers (64 regs)
    const int cwid = (wid < 8) ? wid : wid - 8;
    const int q = cwid & 3;          // col quarter
    const int chalf = cwid >> 2;     // row half (blocks 4*chalf .. +4)
    uint32_t wr[8][2][4];
    {
        uint32_t wimg = sb + ((wid < 8) ? SWIMG1 : SWIMG3) + (uint32_t)q * 8192 + laneN;
#pragma unroll
        for (int s = 0; s < 8; s++) {
            uint32_t sw = ((uint32_t)(32 * s) + kl2) ^ xorv;
            LDSM4(wr[s][0][0], wr[s][0][1], wr[s][0][2], wr[s][0][3], wimg + sw);
            LDSM4(wr[s][1][0], wr[s][1][1], wr[s][1][2], wr[s][1][3], wimg + 4096 + sw);
        }
    }
    __syncthreads();   // weight images consumed; h buffers free

    const float* b1s = (const float*)(smem + SB1);
    const float* b2s = (const float*)(smem + SB2);
    const float* gms = (const float*)(smem + SGAM);
    const float* bts = (const float*)(smem + SBET);
    const int tidp = wid * 32 + l;   // 0..255 for producers

    // ================= pipelined main loop =================
    for (int i = 0; i <= n; i++) {
        const int p = i & 1;
        if (wid < 8) {
            if (i < n) {
                const int t = bx + i * GRID_MAIN;
                // ---- stage x(t) into SXH/SXL (coalesced LDG.128) ----
                const float4* xp = (const float4*)(x + (size_t)t * (128 * D));
#pragma unroll
                for (int ii = 0; ii < 16; ii++) {
                    int idx4 = tidp + 256 * ii;
                    int row = idx4 >> 5;
                    int c4 = (idx4 & 31) * 4;
                    float4 v = xp[idx4];
                    uint32_t h0, l0, h1, l1;
                    split2h(v.x, v.y, h0, l0);
                    split2h(v.z, v.w, h1, l1);
                    uint32_t off = (uint32_t)(row * 256) +
                                   (((uint32_t)(c4 * 2)) ^ (((uint32_t)row & 7u) << 4));
                    *(uint2*)(smem + SXH + off) = make_uint2(h0, h1);
                    *(uint2*)(smem + SXL + off) = make_uint2(l0, l1);
                }
                BARN(3, 256);   // producers: x image ready

                // ---- GEMM1 on 4 row-blocks -> gelu -> h[p] ----
                char* hpH = smem + (p ? SH1H : SH0H);
                char* hpL = smem + (p ? SH1L : SH0L);
                for (int b = 0; b < 4; b++) {
                    const int rb = chalf * 4 + b;
                    float c1[4][4];
#pragma unroll
                    for (int j = 0; j < 4; j++) {
                        float2 bb = *(const float2*)(b1s + q * 32 + 8 * j + qid * 2);
                        c1[j][0] = bb.x; c1[j][1] = bb.y; c1[j][2] = bb.x; c1[j][3] = bb.y;
                    }
#pragma unroll
                    for (int s = 0; s < 8; s++) {
                        uint32_t ao = (uint32_t)(rb * 4096) + aoff +
                                      (((uint32_t)(32 * s) + akadd) ^ axor);
                        uint32_t aH[4], aL[4];
                        LDSM4(aH[0], aH[1], aH[2], aH[3], sb + SXH + ao);
                        LDSM4(aL[0], aL[1], aL[2], aL[3], sb + SXL + ao);
#pragma unroll
                        for (int j = 0; j < 2; j++) {
                            MMA(c1[2 * j][0], c1[2 * j][1], c1[2 * j][2], c1[2 * j][3],
                                aH[0], aH[1], aH[2], aH[3], wr[s][j][0], wr[s][j][1]);
                            MMA(c1[2 * j + 1][0], c1[2 * j + 1][1], c1[2 * j + 1][2], c1[2 * j + 1][3],
                                aH[0], aH[1], aH[2], aH[3], wr[s][j][2], wr[s][j][3]);
                            MMA(c1[2 * j][0], c1[2 * j][1], c1[2 * j][2], c1[2 * j][3],
                                aL[0], aL[1], aL[2], aL[3], wr[s][j][0], wr[s][j][1]);
                            MMA(c1[2 * j + 1][0], c1[2 * j + 1][1], c1[2 * j + 1][2], c1[2 * j + 1][3],
                                aL[0], aL[1], aL[2], aL[3], wr[s][j][2], wr[s][j][3]);
                        }
                    }
                    // gelu + fp16 split -> h[p] A-image
                    const uint32_t rowA = (uint32_t)(rb * 16 + quad);
                    const uint32_t rowB = rowA + 8;
#pragma unroll
                    for (int j = 0; j < 4; j++) {
                        uint32_t kb = (uint32_t)((q * 32 + 8 * j + 2 * qid) * 2);
                        float v0 = gelu_exact(c1[j][0]);
                        float v1 = gelu_exact(c1[j][1]);
                        float v2 = gelu_exact(c1[j][2]);
                        float v3 = gelu_exact(c1[j][3]);
                        uint32_t hA, lA, hB, lB;
                        split2h(v0, v1, hA, lA);
                        split2h(v2, v3, hB, lB);
                        uint32_t offA = rowA * 256 + (kb ^ ((uint32_t)quad << 4));
                        uint32_t offB = rowB * 256 + (kb ^ ((uint32_t)quad << 4));
                        *(uint32_t*)(hpH + offA) = hA;
                        *(uint32_t*)(hpL + offA) = lA;
                        *(uint32_t*)(hpH + offB) = hB;
                        *(uint32_t*)(hpL + offB) = lB;
                    }
                }
            }
        } else {
            if (i > 0) {
                const int tprev = bx + (i - 1) * GRID_MAIN;
                const uint32_t hbH = sb + (p ? SH0H : SH1H);   // h[p^1]
                const uint32_t hbL = sb + (p ? SH0L : SH1L);
                for (int b = 0; b < 4; b++) {
                    const int rb = chalf * 4 + b;
                    float c2[4][4];
#pragma unroll
                    for (int j = 0; j < 4; j++) {
                        float2 bb = *(const float2*)(b2s + q * 32 + 8 * j + qid * 2);
                        c2[j][0] = bb.x; c2[j][1] = bb.y; c2[j][2] = bb.x; c2[j][3] = bb.y;
                    }
#pragma unroll
                    for (int s = 0; s < 8; s++) {
                        uint32_t ao = (uint32_t)(rb * 4096) + aoff +
                                      (((uint32_t)(32 * s) + akadd) ^ axor);
                        uint32_t aH[4], aL[4];
                        LDSM4(aH[0], aH[1], aH[2], aH[3], hbH + ao);
                        LDSM4(aL[0], aL[1], aL[2], aL[3], hbL + ao);
#pragma unroll
                        for (int j = 0; j < 2; j++) {
                            MMA(c2[2 * j][0], c2[2 * j][1], c2[2 * j][2], c2[2 * j][3],
                                aH[0], aH[1], aH[2], aH[3], wr[s][j][0], wr[s][j][1]);
                            MMA(c2[2 * j + 1][0], c2[2 * j + 1][1], c2[2 * j + 1][2], c2[2 * j + 1][3],
                                aH[0], aH[1], aH[2], aH[3], wr[s][j][2], wr[s][j][3]);
                            MMA(c2[2 * j][0], c2[2 * j][1], c2[2 * j][2], c2[2 * j][3],
                                aL[0], aL[1], aL[2], aL[3], wr[s][j][0], wr[s][j][1]);
                            MMA(c2[2 * j + 1][0], c2[2 * j + 1][1], c2[2 * j + 1][2], c2[2 * j + 1][3],
                                aL[0], aL[1], aL[2], aL[3], wr[s][j][2], wr[s][j][3]);
                        }
                    }
                    // LayerNorm: quad bfly + cross-quarter exchange
                    float sA = 0.f, qA = 0.f, sB = 0.f, qB = 0.f;
#pragma unroll
                    for (int j = 0; j < 4; j++) {
                        sA += c2[j][0] + c2[j][1];
                        qA += c2[j][0] * c2[j][0] + c2[j][1] * c2[j][1];
                        sB += c2[j][2] + c2[j][3];
                        qB += c2[j][2] * c2[j][2] + c2[j][3] * c2[j][3];
                    }
#pragma unroll
                    for (int m = 1; m < 4; m <<= 1) {
                        sA += __shfl_xor_sync(0xFFFFFFFFu, sA, m);
                        qA += __shfl_xor_sync(0xFFFFFFFFu, qA, m);
                        sB += __shfl_xor_sync(0xFFFFFFFFu, sB, m);
                        qB += __shfl_xor_sync(0xFFFFFFFFu, qB, m);
                    }
                    if (qid == 0) {
                        *(float4*)(smem + SRED + (((rb * 8 + quad) * 4 + q) << 4)) =
                            make_float4(sA, qA, sB, qB);
                    }
                    BARN(1 + chalf, 128);
                    sA = 0.f; qA = 0.f; sB = 0.f; qB = 0.f;
#pragma unroll
                    for (int w = 0; w < 4; w++) {
                        float4 o = *(const float4*)(smem + SRED + (((rb * 8 + quad) * 4 + w) << 4));
                        sA += o.x; qA += o.y; sB += o.z; qB += o.w;
                    }
                    float mnA = sA * (1.0f / 128.0f);
                    float iA = rsqrtf(qA * (1.0f / 128.0f) - mnA * mnA + 1e-5f);
                    float mnB = sB * (1.0f / 128.0f);
                    float iB = rsqrtf(qB * (1.0f / 128.0f) - mnB * mnB + 1e-5f);

                    const int mArow = rb * 16 + quad;
                    float* oA = out + (size_t)tprev * (128 * D) + (size_t)mArow * D;
                    float* oB = oA + 8 * D;
#pragma unroll
                    for (int j = 0; j < 4; j++) {
                        int n0 = q * 32 + 8 * j + qid * 2;
                        float2 gm = *(const float2*)(gms + n0);
                        float2 bt = *(const float2*)(bts + n0);
                        float2 rA, rB;
                        rA.x = (c2[j][0] - mnA) * iA * gm.x + bt.x;
                        rA.y = (c2[j][1] - mnA) * iA * gm.y + bt.y;
                        rB.x = (c2[j][2] - mnB) * iB * gm.x + bt.x;
                        rB.y = (c2[j][3] - mnB) * iB * gm.y + bt.y;
                        *(float2*)(oA + n0) = rA;
                        *(float2*)(oB + n0) = rB;
                    }
                }
            }
        }
        __syncthreads();
    }
}

// ===================== launch (single kernel per call) =====================
extern "C" void kernel_launch(void* const* d_in, const int* in_sizes, int n_in,
                              void* d_out, int out_size) {
    const float* x     = (const float*)d_in[0];
    const float* graph = (const float*)d_in[1];
    const float* W_msg = (const float*)d_in[2];
    const float* b_msg = (const float*)d_in[3];
    const float* W_upd = (const float*)d_in[4];
    const float* b_upd = (const float*)d_in[5];
    const float* W_out = (const float*)d_in[6];
    const float* b_out = (const float*)d_in[7];
    const float* gamma = (const float*)d_in[8];
    const float* beta  = (const float*)d_in[9];
    float* out = (float*)d_out;

    cudaFuncSetAttribute(lgn_main, cudaFuncAttributeMaxDynamicSharedMemorySize, SMEM_BYTES);

    lgn_main<<<GRID_MAIN, NTHREADS, SMEM_BYTES>>>(
        x, graph, W_msg, b_msg, W_upd, b_upd, W_out, b_out, gamma, beta, out);
}